// round 9
// baseline (speedup 1.0000x reference)
#include <cuda_runtime.h>
#include <cuda_bf16.h>
#include <math.h>
#include <stdint.h>

// ---------------- problem constants ----------------
#define BB   8192
#define KK   10
#define DD   128
#define TT   128
#define QDIM 256            // D + T
#define KDIM 384            // D + D + T
#define MU   (BB + BB*KK)   // 90112 rows in fused layer-1 pass
#define MKU  (MU*KK)        // 901120 neighbor pairs, layer-1
#define MKC  (BB*KK)        // 81920 neighbor pairs, layer-2

typedef __nv_bfloat16  bf16;
typedef __nv_bfloat162 bf162;

// ---------------- scratch (device globals; no allocations allowed) ----------------
__device__ __align__(16) bf16  g_src_h[(size_t)MU*DD],   g_src_l[(size_t)MU*DD];
__device__ __align__(16) float g_q   [(size_t)MU*QDIM];
__device__ __align__(16) bf16  g_kv_h[(size_t)MKU*KDIM], g_kv_l[(size_t)MKU*KDIM];
__device__ __align__(16) float g_k   [(size_t)MKU*QDIM];
__device__ __align__(16) float g_v   [(size_t)MKU*QDIM];
__device__ __align__(16) bf16  g_ctx_h[(size_t)MU*QDIM], g_ctx_l[(size_t)MU*QDIM];
__device__ __align__(16) float g_o   [(size_t)MU*QDIM];
__device__ __align__(16) bf16  g_gg_h[(size_t)MU*KDIM],  g_gg_l[(size_t)MU*KDIM];
__device__ __align__(16) bf16  g_h_h [(size_t)MU*DD],    g_h_l [(size_t)MU*DD];
__device__ __align__(16) bf16  g_o1_h[(size_t)MU*DD],    g_o1_l[(size_t)MU*DD];
__device__ __align__(16) float g_qb  [2*QDIM];
__device__ unsigned char g_inv[MU];
// weight planes (hi/lo bf16, packed to the K actually used by each GEMM)
__device__ __align__(16) bf16 w_q_h[2*QDIM*DD],   w_q_l[2*QDIM*DD];     // Wq cols 0..127 only
__device__ __align__(16) bf16 w_k_h[2*QDIM*KDIM], w_k_l[2*QDIM*KDIM];
__device__ __align__(16) bf16 w_v_h[2*QDIM*KDIM], w_v_l[2*QDIM*KDIM];
__device__ __align__(16) bf16 w_o_h[2*QDIM*QDIM], w_o_l[2*QDIM*QDIM];
__device__ __align__(16) bf16 w_1_h[2*DD*KDIM],   w_1_l[2*DD*KDIM];
__device__ __align__(16) bf16 w_2_h[2*DD*DD],     w_2_l[2*DD*DD];

// ---------------- helpers ----------------
__device__ __forceinline__ void cp_async16(uint32_t s, const void* g) {
    asm volatile("cp.async.cg.shared.global [%0], [%1], 16;" :: "r"(s), "l"(g));
}
__device__ __forceinline__ void mma16(float* c, const uint32_t* a, const uint32_t* b) {
    asm volatile("mma.sync.aligned.m16n8k16.row.col.f32.bf16.bf16.f32 "
        "{%0,%1,%2,%3},{%4,%5,%6,%7},{%8,%9},{%0,%1,%2,%3};"
        : "+f"(c[0]), "+f"(c[1]), "+f"(c[2]), "+f"(c[3])
        : "r"(a[0]), "r"(a[1]), "r"(a[2]), "r"(a[3]), "r"(b[0]), "r"(b[1]));
}
__device__ __forceinline__ void ldsm_x4(uint32_t* r, uint32_t saddr) {
    asm volatile("ldmatrix.sync.aligned.m8n8.x4.shared.b16 {%0,%1,%2,%3}, [%4];"
        : "=r"(r[0]), "=r"(r[1]), "=r"(r[2]), "=r"(r[3]) : "r"(saddr));
}
__device__ __forceinline__ void split1(float x, bf16* hp, bf16* lp) {
    bf16 h = __float2bfloat16(x);
    *hp = h; *lp = __float2bfloat16(x - __bfloat162float(h));
}
__device__ __forceinline__ void split4(bf16* hp, bf16* lp, float4 v) {
    bf16 hx = __float2bfloat16(v.x), hy = __float2bfloat16(v.y);
    bf16 hz = __float2bfloat16(v.z), hw = __float2bfloat16(v.w);
    ((bf162*)hp)[0] = __halves2bfloat162(hx, hy);
    ((bf162*)hp)[1] = __halves2bfloat162(hz, hw);
    ((bf162*)lp)[0] = __halves2bfloat162(__float2bfloat16(v.x - __bfloat162float(hx)),
                                         __float2bfloat16(v.y - __bfloat162float(hy)));
    ((bf162*)lp)[1] = __halves2bfloat162(__float2bfloat16(v.z - __bfloat162float(hz)),
                                         __float2bfloat16(v.w - __bfloat162float(hw)));
}

#define BK    32
#define BKP   40                 // padded smem row (bf16 elems); 80B stride -> ldmatrix conflict-free
#define STG_E (128*BKP)          // narrow: elems per plane per stage

// =============== narrow split-bf16 GEMM (BN=128, 2 CTA/SM) — used for FFN ===============
extern __shared__ bf16 sm_dyn[];

__global__ __launch_bounds__(256, 2)
void gemm_bf16s(const bf16* __restrict__ Ah, const bf16* __restrict__ Al,
                const bf16* __restrict__ B0h, const bf16* __restrict__ B0l, const float* __restrict__ bias0,
                const bf16* __restrict__ B1h, const bf16* __restrict__ B1l, const float* __restrict__ bias1,
                int Nper, int Kd, int relu, int split,
                float* __restrict__ C0f, float* __restrict__ C1f,
                bf16* __restrict__ C0h, bf16* __restrict__ C0l,
                bf16* __restrict__ C1h, bf16* __restrict__ C1l)
{
    const int t  = threadIdx.x;
    const int m0 = blockIdx.y * 128;
    const int nblk = Nper / 128;
    const bf16 *Bh, *Bl; const float* bias; float* Cf; bf16 *Ch, *Cl; int n0;
    if ((int)blockIdx.x < nblk) { Bh=B0h; Bl=B0l; bias=bias0; Cf=C0f; Ch=C0h; Cl=C0l; n0=blockIdx.x*128; }
    else                        { Bh=B1h; Bl=B1l; bias=bias1; Cf=C1f; Ch=C1h; Cl=C1l; n0=(blockIdx.x-nblk)*128; }

    const int warp = t >> 5, lane = t & 31;
    const int wm = (warp & 3) * 32, wn = (warp >> 2) * 64;
    const int g = lane >> 2, tig = lane & 3;
    const int mtx = lane >> 3;

    const int arow = wm + ((mtx & 1) * 8) + (lane & 7);
    const int acol = (mtx & 2) * 4;
    const int brow = wn + ((mtx >> 1) * 8) + (lane & 7);
    const int bcol = (mtx & 1) * 8;
    const uint32_t aoff = (uint32_t)(arow * BKP + acol) * 2;
    const uint32_t boff = (uint32_t)(brow * BKP + bcol) * 2;

    const bf16* Abh = Ah + (size_t)m0 * Kd;
    const bf16* Abl = Al + (size_t)m0 * Kd;
    const bf16* Bbh = Bh + (size_t)n0 * Kd;
    const bf16* Bbl = Bl + (size_t)n0 * Kd;

    const uint32_t s0 = (uint32_t)__cvta_generic_to_shared(sm_dyn);
    const int nK = Kd / BK;

    auto issue = [&](int kt, int buf) {
        const int ko = kt * BK;
        const uint32_t stg = s0 + (uint32_t)buf * (STG_E * 2);
        #pragma unroll
        for (int c = t; c < 512; c += 256) {
            const int r = c >> 2, off = (c & 3) * 8;
            const uint32_t da = (uint32_t)((r * BKP + off) * 2);
            const size_t gof = (size_t)r * Kd + ko + off;
            cp_async16(stg + da,               Abh + gof);
            cp_async16(stg + 4*STG_E + da,     Abl + gof);
            cp_async16(stg + 8*STG_E + da,     Bbh + gof);
            cp_async16(stg + 12*STG_E + da,    Bbl + gof);
        }
        asm volatile("cp.async.commit_group;" ::: "memory");
    };

    float acc[2][8][4];
    #pragma unroll
    for (int mi = 0; mi < 2; mi++)
        #pragma unroll
        for (int ni = 0; ni < 8; ni++)
            #pragma unroll
            for (int x = 0; x < 4; x++) acc[mi][ni][x] = 0.f;

    issue(0, 0);
    for (int kt = 0; kt < nK; kt++) {
        const int buf = kt & 1;
        if (kt + 1 < nK) { issue(kt + 1, buf ^ 1); asm volatile("cp.async.wait_group 1;" ::: "memory"); }
        else             { asm volatile("cp.async.wait_group 0;" ::: "memory"); }
        __syncthreads();
        const uint32_t bAh = s0 + (uint32_t)(0 + buf) * (STG_E * 2);
        const uint32_t bAl = s0 + (uint32_t)(2 + buf) * (STG_E * 2);
        const uint32_t bBh = s0 + (uint32_t)(4 + buf) * (STG_E * 2);
        const uint32_t bBl = s0 + (uint32_t)(6 + buf) * (STG_E * 2);
        #pragma unroll
        for (int kk = 0; kk < BK; kk += 16) {
            const uint32_t kb = (uint32_t)kk * 2;
            uint32_t ah[2][4], ax[2][4], bx[4][4];
            #pragma unroll
            for (int mi = 0; mi < 2; mi++)
                ldsm_x4(ah[mi], bAh + aoff + (uint32_t)(mi * 16 * BKP) * 2 + kb);
            #pragma unroll
            for (int nj = 0; nj < 4; nj++)
                ldsm_x4(bx[nj], bBh + boff + (uint32_t)(nj * 16 * BKP) * 2 + kb);
            #pragma unroll
            for (int mi = 0; mi < 2; mi++)
                #pragma unroll
                for (int ni = 0; ni < 8; ni++)
                    mma16(acc[mi][ni], ah[mi], &bx[ni >> 1][(ni & 1) * 2]);   // hi*hi
            #pragma unroll
            for (int mi = 0; mi < 2; mi++)
                ldsm_x4(ax[mi], bAl + aoff + (uint32_t)(mi * 16 * BKP) * 2 + kb);
            #pragma unroll
            for (int mi = 0; mi < 2; mi++)
                #pragma unroll
                for (int ni = 0; ni < 8; ni++)
                    mma16(acc[mi][ni], ax[mi], &bx[ni >> 1][(ni & 1) * 2]);   // lo*hi
            #pragma unroll
            for (int nj = 0; nj < 4; nj++)
                ldsm_x4(bx[nj], bBl + boff + (uint32_t)(nj * 16 * BKP) * 2 + kb);
            #pragma unroll
            for (int mi = 0; mi < 2; mi++)
                #pragma unroll
                for (int ni = 0; ni < 8; ni++)
                    mma16(acc[mi][ni], ah[mi], &bx[ni >> 1][(ni & 1) * 2]);   // hi*lo
        }
        __syncthreads();
    }

    #pragma unroll
    for (int mi = 0; mi < 2; mi++) {
        const int row0 = m0 + wm + mi*16 + g;
        #pragma unroll
        for (int ni = 0; ni < 8; ni++) {
            const int col = n0 + wn + ni*8 + 2*tig;
            const float b0v = bias[col], b1v = bias[col + 1];
            float v0 = acc[mi][ni][0] + b0v, v1 = acc[mi][ni][1] + b1v;
            float v2 = acc[mi][ni][2] + b0v, v3 = acc[mi][ni][3] + b1v;
            if (relu) { v0 = fmaxf(v0,0.f); v1 = fmaxf(v1,0.f); v2 = fmaxf(v2,0.f); v3 = fmaxf(v3,0.f); }
            if (!split) {
                *(float2*)(Cf + (size_t)row0 * Nper + col)     = make_float2(v0, v1);
                *(float2*)(Cf + (size_t)(row0+8) * Nper + col) = make_float2(v2, v3);
            } else {
                bf16 h0 = __float2bfloat16(v0), h1 = __float2bfloat16(v1);
                bf16 h2 = __float2bfloat16(v2), h3 = __float2bfloat16(v3);
                *(bf162*)(Ch + (size_t)row0 * Nper + col)     = __halves2bfloat162(h0, h1);
                *(bf162*)(Ch + (size_t)(row0+8) * Nper + col) = __halves2bfloat162(h2, h3);
                *(bf162*)(Cl + (size_t)row0 * Nper + col)     =
                    __halves2bfloat162(__float2bfloat16(v0 - __bfloat162float(h0)),
                                       __float2bfloat16(v1 - __bfloat162float(h1)));
                *(bf162*)(Cl + (size_t)(row0+8) * Nper + col) =
                    __halves2bfloat162(__float2bfloat16(v2 - __bfloat162float(h2)),
                                       __float2bfloat16(v3 - __bfloat162float(h3)));
            }
        }
    }
}

// =============== wide split-bf16 GEMM (BN=256, 1 CTA/SM) — Q / KV / O ===============
// Halves A DRAM re-reads: each CTA computes a full 256-col output block.
// smem bytes: A hi/lo 2 stages x 10240 each (0..40960), B hi/lo 2 stages x 20480 (40960..122880)
#define W_A_STG 10240
#define W_B_STG 20480
#define W_SMEM  122880

__global__ __launch_bounds__(256, 1)
void gemm_bf16w(const bf16* __restrict__ Ah, const bf16* __restrict__ Al,
                const bf16* __restrict__ B0h, const bf16* __restrict__ B0l, const float* __restrict__ bias0,
                const bf16* __restrict__ B1h, const bf16* __restrict__ B1l, const float* __restrict__ bias1,
                int Nper, int Kd, int relu,
                float* __restrict__ C0f, float* __restrict__ C1f)
{
    const int t  = threadIdx.x;
    const int m0 = blockIdx.y * 128;
    const int nblk = Nper / 256;
    const bf16 *Bh, *Bl; const float* bias; float* Cf; int n0;
    if ((int)blockIdx.x < nblk) { Bh=B0h; Bl=B0l; bias=bias0; Cf=C0f; n0=blockIdx.x*256; }
    else                        { Bh=B1h; Bl=B1l; bias=bias1; Cf=C1f; n0=(blockIdx.x-nblk)*256; }

    const int warp = t >> 5, lane = t & 31;
    const int wm = (warp & 3) * 32, wn = (warp >> 2) * 128;
    const int g = lane >> 2, tig = lane & 3;
    const int mtx = lane >> 3;

    const int arow = wm + ((mtx & 1) * 8) + (lane & 7);
    const int acol = (mtx & 2) * 4;
    const int brow = wn + ((mtx >> 1) * 8) + (lane & 7);
    const int bcol = (mtx & 1) * 8;
    const uint32_t aoff = (uint32_t)(arow * BKP + acol) * 2;
    const uint32_t boff = (uint32_t)(brow * BKP + bcol) * 2;

    const bf16* Abh = Ah + (size_t)m0 * Kd;
    const bf16* Abl = Al + (size_t)m0 * Kd;
    const bf16* Bbh = Bh + (size_t)n0 * Kd;
    const bf16* Bbl = Bl + (size_t)n0 * Kd;

    const uint32_t s0 = (uint32_t)__cvta_generic_to_shared(sm_dyn);
    const int nK = Kd / BK;

    auto issue = [&](int kt, int buf) {
        const int ko = kt * BK;
        #pragma unroll
        for (int c = t; c < 512; c += 256) {               // A: 128 rows x 4 chunks
            const int r = c >> 2, off = (c & 3) * 8;
            const uint32_t da = (uint32_t)((r * BKP + off) * 2);
            const size_t gof = (size_t)r * Kd + ko + off;
            cp_async16(s0 + (uint32_t)buf*W_A_STG + da,           Abh + gof);
            cp_async16(s0 + 2*W_A_STG + (uint32_t)buf*W_A_STG + da, Abl + gof);
        }
        #pragma unroll
        for (int c = t; c < 1024; c += 256) {              // B: 256 rows x 4 chunks
            const int r = c >> 2, off = (c & 3) * 8;
            const uint32_t da = (uint32_t)((r * BKP + off) * 2);
            const size_t gof = (size_t)r * Kd + ko + off;
            cp_async16(s0 + 4*W_A_STG + (uint32_t)buf*W_B_STG + da,             Bbh + gof);
            cp_async16(s0 + 4*W_A_STG + 2*W_B_STG + (uint32_t)buf*W_B_STG + da, Bbl + gof);
        }
        asm volatile("cp.async.commit_group;" ::: "memory");
    };

    float acc[2][16][4];
    #pragma unroll
    for (int mi = 0; mi < 2; mi++)
        #pragma unroll
        for (int ni = 0; ni < 16; ni++)
            #pragma unroll
            for (int x = 0; x < 4; x++) acc[mi][ni][x] = 0.f;

    issue(0, 0);
    for (int kt = 0; kt < nK; kt++) {
        const int buf = kt & 1;
        if (kt + 1 < nK) { issue(kt + 1, buf ^ 1); asm volatile("cp.async.wait_group 1;" ::: "memory"); }
        else             { asm volatile("cp.async.wait_group 0;" ::: "memory"); }
        __syncthreads();
        const uint32_t bAh = s0 + (uint32_t)buf * W_A_STG;
        const uint32_t bAl = s0 + 2*W_A_STG + (uint32_t)buf * W_A_STG;
        const uint32_t bBh = s0 + 4*W_A_STG + (uint32_t)buf * W_B_STG;
        const uint32_t bBl = s0 + 4*W_A_STG + 2*W_B_STG + (uint32_t)buf * W_B_STG;
        #pragma unroll
        for (int kk = 0; kk < BK; kk += 16) {
            const uint32_t kb = (uint32_t)kk * 2;
            uint32_t ah[2][4], ax[2][4], bx[8][4];
            #pragma unroll
            for (int mi = 0; mi < 2; mi++)
                ldsm_x4(ah[mi], bAh + aoff + (uint32_t)(mi * 16 * BKP) * 2 + kb);
            #pragma unroll
            for (int nj = 0; nj < 8; nj++)
                ldsm_x4(bx[nj], bBh + boff + (uint32_t)(nj * 16 * BKP) * 2 + kb);
            #pragma unroll
            for (int mi = 0; mi < 2; mi++)
                #pragma unroll
                for (int ni = 0; ni < 16; ni++)
                    mma16(acc[mi][ni], ah[mi], &bx[ni >> 1][(ni & 1) * 2]);   // hi*hi
            #pragma unroll
            for (int mi = 0; mi < 2; mi++)
                ldsm_x4(ax[mi], bAl + aoff + (uint32_t)(mi * 16 * BKP) * 2 + kb);
            #pragma unroll
            for (int mi = 0; mi < 2; mi++)
                #pragma unroll
                for (int ni = 0; ni < 16; ni++)
                    mma16(acc[mi][ni], ax[mi], &bx[ni >> 1][(ni & 1) * 2]);   // lo*hi
            #pragma unroll
            for (int nj = 0; nj < 8; nj++)
                ldsm_x4(bx[nj], bBl + boff + (uint32_t)(nj * 16 * BKP) * 2 + kb);
            #pragma unroll
            for (int mi = 0; mi < 2; mi++)
                #pragma unroll
                for (int ni = 0; ni < 16; ni++)
                    mma16(acc[mi][ni], ah[mi], &bx[ni >> 1][(ni & 1) * 2]);   // hi*lo
        }
        __syncthreads();
    }

    #pragma unroll
    for (int mi = 0; mi < 2; mi++) {
        const int row0 = m0 + wm + mi*16 + g;
        #pragma unroll
        for (int ni = 0; ni < 16; ni++) {
            const int col = n0 + wn + ni*8 + 2*tig;
            const float b0v = bias[col], b1v = bias[col + 1];
            float v0 = acc[mi][ni][0] + b0v, v1 = acc[mi][ni][1] + b1v;
            float v2 = acc[mi][ni][2] + b0v, v3 = acc[mi][ni][3] + b1v;
            if (relu) { v0 = fmaxf(v0,0.f); v1 = fmaxf(v1,0.f); v2 = fmaxf(v2,0.f); v3 = fmaxf(v3,0.f); }
            *(float2*)(Cf + (size_t)row0 * Nper + col)     = make_float2(v0, v1);
            *(float2*)(Cf + (size_t)(row0+8) * Nper + col) = make_float2(v2, v3);
        }
    }
}

// ---------------- weight splitter: packed [rows, cols] hi/lo from fp32 [rows, ld] ----------------
__global__ void split_w(const float* __restrict__ src, bf16* __restrict__ hi, bf16* __restrict__ lo,
                        int total, int cols, int ld)
{
    const int i = blockIdx.x * 256 + threadIdx.x;
    if (i >= total) return;
    const int r = i / cols, c = i - r * cols;
    split1(src[(size_t)r * ld + c], hi + i, lo + i);
}

// ---------------- effective Q bias: qb[model][n] = bq[n] + sum_t Wq[n][128+t]*cos(tb[t]) ----------------
__global__ void make_qbias(const float* __restrict__ Wq, const float* __restrict__ bq,
                           const float* __restrict__ tb, float* __restrict__ qb)
{
    const int model = blockIdx.x, n = threadIdx.x;     // grid 2, block 256
    const float* w = Wq + (size_t)model * QDIM * QDIM + (size_t)n * QDIM + DD;
    float s = bq[model * QDIM + n];
    for (int t = 0; t < TT; t++) s += w[t] * cosf(tb[t]);
    qb[model * QDIM + n] = s;
}

// ---------------- gather emb0 for layer-1 src rows ----------------
__global__ void gather_src_l1(const float* __restrict__ nf, const float* __restrict__ mem,
                              const int* __restrict__ src_nodes, const int* __restrict__ n1flat,
                              bf16* __restrict__ dh, bf16* __restrict__ dl)
{
    const int m = blockIdx.x * 4 + (threadIdx.x >> 5);
    const int lane = threadIdx.x & 31;
    const int node = (m < BB) ? src_nodes[m] : n1flat[m - BB];
    const float4 a = ((const float4*)(nf  + (size_t)node * DD))[lane];
    const float4 b = ((const float4*)(mem + (size_t)node * DD))[lane];
    split4(dh + (size_t)m*DD + lane*4, dl + (size_t)m*DD + lane*4,
           make_float4(a.x+b.x, a.y+b.y, a.z+b.z, a.w+b.w));
}

// ---------------- keyv rows, layer-1 fused pass ----------------
__global__ void build_keyv_l1(const float* __restrict__ nf, const float* __restrict__ mem,
                              const float* __restrict__ ef,
                              const float* __restrict__ tw, const float* __restrict__ tb,
                              const int* __restrict__ n1, const int* __restrict__ e1,
                              const float* __restrict__ et1, const float* __restrict__ ts,
                              const int* __restrict__ n2, const int* __restrict__ e2,
                              const float* __restrict__ et2,
                              bf16* __restrict__ kvh, bf16* __restrict__ kvl)
{
    const int p = blockIdx.x * 4 + (threadIdx.x >> 5);
    const int lane = threadIdx.x & 31;
    const int m = p / KK;
    int node, eidx; float tm, et;
    if (m < BB) { node = n1[p]; eidx = e1[p]; tm = ts[m]; et = et1[p]; }
    else {
        const int pp = p - BB * KK;
        node = n2[pp]; eidx = e2[pp]; tm = ts[(m - BB) / KK]; et = et2[pp];
    }
    const float4 a = ((const float4*)(nf  + (size_t)node * DD))[lane];
    const float4 b = ((const float4*)(mem + (size_t)node * DD))[lane];
    const float4 e = ((const float4*)(ef  + (size_t)eidx * DD))[lane];
    const float4 w = ((const float4*)tw)[lane];
    const float4 bb = ((const float4*)tb)[lane];
    const float dt = tm - et;
    const size_t base = (size_t)p * KDIM + lane*4;
    split4(kvh + base,        kvl + base,        make_float4(a.x+b.x, a.y+b.y, a.z+b.z, a.w+b.w));
    split4(kvh + base + DD,   kvl + base + DD,   e);
    split4(kvh + base + 2*DD, kvl + base + 2*DD,
           make_float4(cosf(dt*w.x+bb.x), cosf(dt*w.y+bb.y), cosf(dt*w.z+bb.z), cosf(dt*w.w+bb.w)));
}

// ---------------- keyv rows, layer-2 pass (neighbor emb copied from out1 planes) ----------------
__global__ void build_keyv_l2(const bf16* __restrict__ nh, const bf16* __restrict__ nl,  // [MKC, DD]
                              const float* __restrict__ ef,
                              const float* __restrict__ tw, const float* __restrict__ tb,
                              const int* __restrict__ e1, const float* __restrict__ et1,
                              const float* __restrict__ ts,
                              bf16* __restrict__ kvh, bf16* __restrict__ kvl)
{
    const int p = blockIdx.x * 4 + (threadIdx.x >> 5);
    const int lane = threadIdx.x & 31;
    const int m = p / KK;
    const float4 e  = ((const float4*)(ef + (size_t)e1[p] * DD))[lane];
    const float4 w  = ((const float4*)tw)[lane];
    const float4 bb = ((const float4*)tb)[lane];
    const float dt = ts[m] - et1[p];
    const size_t base = (size_t)p * KDIM + lane*4;
    ((uint2*)(kvh + (size_t)p*KDIM))[lane] = ((const uint2*)(nh + (size_t)p*DD))[lane];
    ((uint2*)(kvl + (size_t)p*KDIM))[lane] = ((const uint2*)(nl + (size_t)p*DD))[lane];
    split4(kvh + base + DD,   kvl + base + DD,   e);
    split4(kvh + base + 2*DD, kvl + base + 2*DD,
           make_float4(cosf(dt*w.x+bb.x), cosf(dt*w.y+bb.y), cosf(dt*w.z+bb.z), cosf(dt*w.w+bb.w)));
}

// ---------------- scores + masked softmax + context ----------------
__global__ void attn_combine(const float* __restrict__ q, const float* __restrict__ k,
                             const float* __restrict__ v,
                             const int* __restrict__ neighA, const int* __restrict__ neighB,
                             int boundary,
                             bf16* __restrict__ ch, bf16* __restrict__ cl,
                             unsigned char* __restrict__ inv)
{
    const int m = blockIdx.x, t = threadIdx.x;             // 256 threads
    __shared__ int   smask[KK];
    __shared__ float ssc[2][KK];
    __shared__ float sw[2][KK];

    if (t < KK) {
        const int* nb = (m < boundary) ? (neighA + (size_t)m * KK)
                                       : (neighB + (size_t)(m - boundary) * KK);
        smask[t] = (nb[t] == 0);
    }
    const int warp = t >> 5, lane = t & 31;
    for (int task = warp; task < 2 * KK; task += 8) {
        const int j = task >> 1, h = task & 1;
        const float* qr = q + (size_t)m * QDIM + h * 128;
        const float* kr = k + ((size_t)m * KK + j) * QDIM + h * 128;
        float s = 0.f;
        #pragma unroll
        for (int i = 0; i < 4; i++) { const int c = lane + 32 * i; s += qr[c] * kr[c]; }
        #pragma unroll
        for (int o = 16; o; o >>= 1) s += __shfl_xor_sync(0xffffffffu, s, o);
        if (lane == 0) ssc[h][j] = s * 0.08838834764831845f;   // 1/sqrt(128)
    }
    __syncthreads();

    if (t < 2) {
        const int h = t;
        int all1 = 1;
        #pragma unroll
        for (int j = 0; j < KK; j++) all1 &= smask[j];
        float sv[KK]; float mx = -3.0e38f;
        #pragma unroll
        for (int j = 0; j < KK; j++) {
            const int mk = smask[j] && !(all1 && j == 0);
            sv[j] = mk ? -1e9f : ssc[h][j];
            mx = fmaxf(mx, sv[j]);
        }
        float den = 0.f;
        #pragma unroll
        for (int j = 0; j < KK; j++) { const float e = expf(sv[j] - mx); sw[h][j] = e; den += e; }
        const float r = 1.f / den;
        #pragma unroll
        for (int j = 0; j < KK; j++) sw[h][j] *= r;
        if (t == 0) inv[m] = (unsigned char)all1;
    }
    __syncthreads();

    const int h = t >> 7;
    float acc = 0.f;
    #pragma unroll
    for (int j = 0; j < KK; j++)
        acc += sw[h][j] * v[((size_t)m * KK + j) * QDIM + t];
    split1(acc, ch + (size_t)m * QDIM + t, cl + (size_t)m * QDIM + t);
}

// ---------------- g = [invalid ? 0 : o  ||  src_feat] ----------------
__global__ void build_g(const float* __restrict__ o,
                        const bf16* __restrict__ sh, const bf16* __restrict__ sl,
                        const unsigned char* __restrict__ inv,
                        bf16* __restrict__ gh, bf16* __restrict__ gl)
{
    const int m = blockIdx.x, t = threadIdx.x;             // 384 threads
    const size_t idx = (size_t)m * KDIM + t;
    if (t < QDIM) {
        const float val = inv[m] ? 0.f : o[(size_t)m * QDIM + t];
        split1(val, gh + idx, gl + idx);
    } else {
        gh[idx] = sh[(size_t)m * DD + (t - QDIM)];
        gl[idx] = sl[(size_t)m * DD + (t - QDIM)];
    }
}

// ---------------- host launcher ----------------
#define GEMM_SMEM (8 * STG_E * 2)    // 81920 bytes (narrow)

extern "C" void kernel_launch(void* const* d_in, const int* in_sizes, int n_in,
                              void* d_out, int out_size)
{
    const float* node_feat   = (const float*)d_in[0];
    const float* memory      = (const float*)d_in[1];
    const float* edge_feat   = (const float*)d_in[2];
    const float* time_w      = (const float*)d_in[3];
    const float* time_b      = (const float*)d_in[4];
    const float* Wq          = (const float*)d_in[5];
    const float* bq          = (const float*)d_in[6];
    const float* Wk          = (const float*)d_in[7];
    const float* bk          = (const float*)d_in[8];
    const float* Wv          = (const float*)d_in[9];
    const float* bv          = (const float*)d_in[10];
    const float* Wo          = (const float*)d_in[11];
    const float* bo          = (const float*)d_in[12];
    const float* W1          = (const float*)d_in[13];
    const float* b1          = (const float*)d_in[14];
    const float* W2          = (const float*)d_in[15];
    const float* b2          = (const float*)d_in[16];
    const float* timestamps  = (const float*)d_in[17];
    const int*   src_nodes   = (const int*)d_in[18];
    const int*   neighbors1  = (const int*)d_in[19];
    const int*   edge_idx1   = (const int*)d_in[20];
    const float* edge_times1 = (const float*)d_in[21];
    const int*   neighbors2  = (const int*)d_in[22];
    const int*   edge_idx2   = (const int*)d_in[23];
    const float* edge_times2 = (const float*)d_in[24];
    float* out = (float*)d_out;

    bf16 *srch, *srcl, *kvh, *kvl, *ctxh, *ctxl, *ggh, *ggl, *hh, *hl, *o1h, *o1l;
    bf16 *wqh, *wql, *wkh, *wkl, *wvh, *wvl, *woh, *wol, *w1h, *w1l, *w2h, *w2l;
    float *pq, *pk, *pv, *po, *pqb;
    unsigned char* pinv;
    cudaGetSymbolAddress((void**)&srch, g_src_h); cudaGetSymbolAddress((void**)&srcl, g_src_l);
    cudaGetSymbolAddress((void**)&kvh,  g_kv_h);  cudaGetSymbolAddress((void**)&kvl,  g_kv_l);
    cudaGetSymbolAddress((void**)&ctxh, g_ctx_h); cudaGetSymbolAddress((void**)&ctxl, g_ctx_l);
    cudaGetSymbolAddress((void**)&ggh,  g_gg_h);  cudaGetSymbolAddress((void**)&ggl,  g_gg_l);
    cudaGetSymbolAddress((void**)&hh,   g_h_h);   cudaGetSymbolAddress((void**)&hl,   g_h_l);
    cudaGetSymbolAddress((void**)&o1h,  g_o1_h);  cudaGetSymbolAddress((void**)&o1l,  g_o1_l);
    cudaGetSymbolAddress((void**)&wqh,  w_q_h);   cudaGetSymbolAddress((void**)&wql,  w_q_l);
    cudaGetSymbolAddress((void**)&wkh,  w_k_h);   cudaGetSymbolAddress((void**)&wkl,  w_k_l);
    cudaGetSymbolAddress((void**)&wvh,  w_v_h);   cudaGetSymbolAddress((void**)&wvl,  w_v_l);
    cudaGetSymbolAddress((void**)&woh,  w_o_h);   cudaGetSymbolAddress((void**)&wol,  w_o_l);
    cudaGetSymbolAddress((void**)&w1h,  w_1_h);   cudaGetSymbolAddress((void**)&w1l,  w_1_l);
    cudaGetSymbolAddress((void**)&w2h,  w_2_h);   cudaGetSymbolAddress((void**)&w2l,  w_2_l);
    cudaGetSymbolAddress((void**)&pq,   g_q);     cudaGetSymbolAddress((void**)&pk,   g_k);
    cudaGetSymbolAddress((void**)&pv,   g_v);     cudaGetSymbolAddress((void**)&po,   g_o);
    cudaGetSymbolAddress((void**)&pqb,  g_qb);    cudaGetSymbolAddress((void**)&pinv, g_inv);

    cudaFuncSetAttribute(gemm_bf16s, cudaFuncAttributeMaxDynamicSharedMemorySize, GEMM_SMEM);
    cudaFuncSetAttribute(gemm_bf16w, cudaFuncAttributeMaxDynamicSharedMemorySize, W_SMEM);

    // model-1 plane offsets
    const int OQ = QDIM*DD, OK = QDIM*KDIM, OO = QDIM*QDIM, O1 = DD*KDIM, O2 = DD*DD;
    const float* bk1 = bk + QDIM; const float* bv1 = bv + QDIM; const float* bo1 = bo + QDIM;
    const float* b11 = b1 + DD;   const float* b21 = b2 + DD;

    // ======= launch order arranged so the layer-1 KV GEMM is the 6th launch (ncu -s 5 -c 1) =======
    split_w<<<(2*QDIM*KDIM + 255)/256, 256>>>(Wk, wkh, wkl, 2*QDIM*KDIM, KDIM, KDIM);          // 1
    split_w<<<(2*QDIM*KDIM + 255)/256, 256>>>(Wv, wvh, wvl, 2*QDIM*KDIM, KDIM, KDIM);          // 2
    gather_src_l1<<<MU/4, 128>>>(node_feat, memory, src_nodes, neighbors1, srch, srcl);        // 3
    build_keyv_l1<<<MKU/4, 128>>>(node_feat, memory, edge_feat, time_w, time_b,
                                  neighbors1, edge_idx1, edge_times1, timestamps,
                                  neighbors2, edge_idx2, edge_times2, kvh, kvl);               // 4
    make_qbias<<<2, QDIM>>>(Wq, bq, time_b, pqb);                                              // 5
    gemm_bf16w<<<dim3(2, MKU/128), 256, W_SMEM>>>(kvh, kvl, wkh, wkl, bk, wvh, wvl, bv,
        QDIM, KDIM, 0, pk, pv);                                                                // 6 <- profiled
    split_w<<<(2*QDIM*DD + 255)/256, 256>>>(Wq, wqh, wql, 2*QDIM*DD, DD, QDIM);
    gemm_bf16w<<<dim3(1, MU/128), 256, W_SMEM>>>(srch, srcl, wqh, wql, pqb, wqh, wql, pqb,
        QDIM, DD, 0, pq, pq);
    attn_combine<<<MU, 256>>>(pq, pk, pv, neighbors1, neighbors2, BB, ctxh, ctxl, pinv);
    split_w<<<(2*QDIM*QDIM + 255)/256, 256>>>(Wo, woh, wol, 2*QDIM*QDIM, QDIM, QDIM);
    gemm_bf16w<<<dim3(1, MU/128), 256, W_SMEM>>>(ctxh, ctxl, woh, wol, bo, woh, wol, bo,
        QDIM, QDIM, 0, po, po);
    build_g<<<MU, KDIM>>>(po, srch, srcl, pinv, ggh, ggl);
    split_w<<<(2*DD*KDIM + 255)/256, 256>>>(W1, w1h, w1l, 2*DD*KDIM, KDIM, KDIM);
    gemm_bf16s<<<dim3(1, MU/128), 256, GEMM_SMEM>>>(ggh, ggl, w1h, w1l, b1, w1h, w1l, b1,
        DD, KDIM, 1, 1, 0, 0, hh, hl, hh, hl);
    split_w<<<(2*DD*DD + 255)/256, 256>>>(W2, w2h, w2l, 2*DD*DD, DD, DD);
    gemm_bf16s<<<dim3(1, MU/128), 256, GEMM_SMEM>>>(hh, hl, w2h, w2l, b2, w2h, w2l, b2,
        DD, DD, 0, 1, 0, 0, o1h, o1l, o1h, o1l);

    // ================= layer-2 pass (model 1), M = BB =================
    gemm_bf16w<<<dim3(1, BB/128), 256, W_SMEM>>>(o1h, o1l, wqh+OQ, wql+OQ, pqb+QDIM, wqh+OQ, wql+OQ, pqb+QDIM,
        QDIM, DD, 0, pq, pq);
    build_keyv_l2<<<MKC/4, 128>>>(o1h + (size_t)BB*DD, o1l + (size_t)BB*DD, edge_feat, time_w, time_b,
                                  edge_idx1, edge_times1, timestamps, kvh, kvl);
    gemm_bf16w<<<dim3(2, MKC/128), 256, W_SMEM>>>(kvh, kvl, wkh+OK, wkl+OK, bk1, wvh+OK, wvl+OK, bv1,
        QDIM, KDIM, 0, pk, pv);
    attn_combine<<<BB, 256>>>(pq, pk, pv, neighbors1, neighbors1, BB, ctxh, ctxl, pinv);
    gemm_bf16w<<<dim3(1, BB/128), 256, W_SMEM>>>(ctxh, ctxl, woh+OO, wol+OO, bo1, woh+OO, wol+OO, bo1,
        QDIM, QDIM, 0, po, po);
    build_g<<<BB, KDIM>>>(po, o1h, o1l, pinv, ggh, ggl);
    gemm_bf16s<<<dim3(1, BB/128), 256, GEMM_SMEM>>>(ggh, ggl, w1h+O1, w1l+O1, b11, w1h+O1, w1l+O1, b11,
        DD, KDIM, 1, 1, 0, 0, hh, hl, hh, hl);
    gemm_bf16s<<<dim3(1, BB/128), 256, GEMM_SMEM>>>(hh, hl, w2h+O2, w2l+O2, b21, w2h+O2, w2l+O2, b21,
        DD, DD, 0, 0, out, out, 0, 0, 0, 0);
}